// round 17
// baseline (speedup 1.0000x reference)
#include <cuda_runtime.h>
#include <stdint.h>

// AE_spikes via mma.sync s8 tensor cores. R9 architecture (measured 919.5us,
// the best configuration) with three orthogonal deltas: launch_bounds(256,3)
// on the gemm kernels (smem already allowed 3 CTAs/SM; R9 was bound-capped),
// E-trick combine (E=254*D0+D1, single I2F), and merged wsplit launch.
// Everything else byte-identical to the R9 winner: smem A panel expansion,
// scalar fragment loads, pitch-144 B, flag + bit-exact t-parallel repair.

#define BATCH  16384
#define TSTEPS 16
#define KP1    896
#define EPS    1e-3f
#define FCAP   1048576

// ---------------- scratch ----------------
__device__ uint16_t g_M0[BATCH * KP1];
__device__ uint16_t g_M1[BATCH * 128];
__device__ uint16_t g_M2[BATCH * 128];
__device__ uint16_t g_M3[BATCH * 128];
__device__ int8_t   g_Q1[2 * 128 * KP1];
__device__ int8_t   g_Q2[2 * 128 * 128];
__device__ int8_t   g_Q3[2 * 128 * 128];
__device__ int8_t   g_Q4[2 * 784 * 128];
__device__ float    g_S1[128], g_S2[128], g_S3[128], g_S4[784];
__device__ int      g_cnt[4];
__device__ uint32_t g_flag[4][FCAP];

// ---------------- helpers ----------------
__device__ __forceinline__ uint32_t smem_u32(const void* p) {
    uint32_t a;
    asm("{ .reg .u64 t; cvta.to.shared.u64 t, %1; cvt.u32.u64 %0, t; }"
        : "=r"(a) : "l"(p));
    return a;
}
__device__ __forceinline__ void mma8(int* d, const uint32_t* a, uint32_t b0, uint32_t b1) {
    asm volatile(
        "mma.sync.aligned.m16n8k32.row.col.s32.s8.s8.s32 "
        "{%0,%1,%2,%3}, {%4,%5,%6,%7}, {%8,%9}, {%0,%1,%2,%3};"
        : "+r"(d[0]), "+r"(d[1]), "+r"(d[2]), "+r"(d[3])
        : "r"(a[0]), "r"(a[1]), "r"(a[2]), "r"(a[3]), "r"(b0), "r"(b1));
}
__device__ __forceinline__ void cpa16(uint32_t dst, const void* src, uint32_t ssz) {
    asm volatile("cp.async.cg.shared.global [%0], [%1], 16, %2;"
                 :: "r"(dst), "l"(src), "r"(ssz));
}

__global__ void zero_cnt_kernel() { if (threadIdx.x < 4) g_cnt[threadIdx.x] = 0; }

// ---------------- encoder (bit-exact) ----------------
__global__ void __launch_bounds__(256) enc_kernel(const float* __restrict__ f) {
    int idx = blockIdx.x * blockDim.x + threadIdx.x;
    if (idx >= BATCH * KP1) return;
    int b = idx / KP1, i = idx - b * KP1;
    unsigned m = 0;
    if (i < 784) {
        float x = f[b * 784 + i], v = 0.0f;
#pragma unroll
        for (int t = 0; t < TSTEPS; t++) {
            v += x;
            if (v >= 1.0f) { m |= (1u << t); v -= 1.0f; }
        }
    }
    g_M0[idx] = (uint16_t)m;
}

// ---------------- weight 2-limb s8 split, base 254 (one launch) -----------
__device__ void wsplit_one(const float* W, int8_t* Q, float* S,
                           int N, int K, int KP, int j, int lane) {
    const float* w = W + (size_t)j * K;
    float m = 0.0f;
    for (int k = lane; k < K; k += 32) m = fmaxf(m, fabsf(w[k]));
#pragma unroll
    for (int o = 16; o; o >>= 1) m = fmaxf(m, __shfl_xor_sync(~0u, m, o));
    float s0 = (m > 0.0f) ? m / 127.0f : 1.0f;
    if (lane == 0) S[j] = s0;
    double s0d = (double)s0;
    for (int k = lane; k < KP; k += 32) {
        double q0 = 0.0, q1 = 0.0;
        if (k < K) {
            double wd = (double)w[k];
            q0 = fmin(fmax(rint(wd / s0d), -127.0), 127.0);
            double r1 = wd - q0 * s0d;
            q1 = fmin(fmax(rint(r1 * 254.0 / s0d), -127.0), 127.0);
        }
        size_t base = (size_t)j * KP + k, lstr = (size_t)N * KP;
        Q[base]        = (int8_t)(int)q0;
        Q[base + lstr] = (int8_t)(int)q1;
    }
}
__global__ void __launch_bounds__(32) wsplit_all(
    const float* __restrict__ W1, const float* __restrict__ W2,
    const float* __restrict__ W3, const float* __restrict__ W4)
{
    int bid = blockIdx.x, lane = threadIdx.x;
    if      (bid < 128) wsplit_one(W1, g_Q1, g_S1, 128, 784, KP1, bid, lane);
    else if (bid < 256) wsplit_one(W2, g_Q2, g_S2, 128, 128, 128, bid - 128, lane);
    else if (bid < 384) wsplit_one(W3, g_Q3, g_S3, 128, 128, 128, bid - 256, lane);
    else                wsplit_one(W4, g_Q4, g_S4, 784, 128, 128, bid - 384, lane);
}

// ---------------- shared device pieces (R9-identical) ----------------
// Masks stored PERMUTED per u64: lo=(m0,m2), hi=(m1,m3). Per t:
//   a=(lo>>t)&0x00010001 ; b=(hi>>t)&0x00010001 ; w = a | (b<<8).
__device__ __forceinline__ void expand_perm(const char* mskbase, char* abase,
                                            int kpu64, int p, int tid) {
    const uint64_t* m64 = (const uint64_t*)mskbase;
    int bl = tid >> 5, kq = tid & 31;
    uint64_t mv = m64[bl * kpu64 + p * 32 + kq];
    uint32_t lo = (uint32_t)mv;
    uint32_t hi = (uint32_t)(mv >> 32);
    char* arow = abase + (bl * 16) * 144 + kq * 4;
#pragma unroll
    for (int t = 0; t < 16; t++) {
        uint32_t a = (lo >> t) & 0x00010001u;
        uint32_t b = (hi >> t) & 0x00010001u;
        *(uint32_t*)(arow + t * 144) = a | (b << 8);
    }
}
__device__ __forceinline__ void expand_unperm(const uint16_t* msk, char* abase, int tid) {
    const uint64_t* m64 = (const uint64_t*)msk;
    int bl = tid >> 5, kq = tid & 31;
    uint64_t mv = m64[bl * 32 + kq];
    uint32_t lo = (uint32_t)mv, hi = (uint32_t)(mv >> 32);
    char* arow = abase + (bl * 16) * 144 + kq * 4;
#pragma unroll
    for (int t = 0; t < 16; t++) {
        uint32_t xl = (lo >> t) & 0x00010001u; xl |= xl >> 15;
        uint32_t xh = (hi >> t) & 0x00010001u; xh |= xh >> 15;
        uint32_t nib = (xl & 3u) | ((xh & 3u) << 2);
        *(uint32_t*)(arow + t * 144) = (nib * 0x00204081u) & 0x01010101u;
    }
}
__device__ __forceinline__ void mma_panel(const char* abase, const char* bbase,
                                          int wm2, int wn, int g, int tg,
                                          int (&D0)[2][4][4], int (&D1)[2][4][4]) {
#pragma unroll
    for (int ch = 0; ch < 4; ch++) {
        uint32_t afr[2][4];
#pragma unroll
        for (int mi = 0; mi < 2; mi++) {
            const char* ab = abase + (wm2 * 32 + mi * 16) * 144 + ch * 32;
            afr[mi][0] = *(const uint32_t*)(ab + g * 144 + tg * 4);
            afr[mi][1] = *(const uint32_t*)(ab + (g + 8) * 144 + tg * 4);
            afr[mi][2] = *(const uint32_t*)(ab + g * 144 + 16 + tg * 4);
            afr[mi][3] = *(const uint32_t*)(ab + (g + 8) * 144 + 16 + tg * 4);
        }
#pragma unroll
        for (int ni = 0; ni < 4; ni++) {
            const char* bb = bbase + (wn * 32 + ni * 8 + g) * 144 + ch * 32;
            uint32_t b00 = *(const uint32_t*)(bb + tg * 4);
            uint32_t b01 = *(const uint32_t*)(bb + 16 + tg * 4);
            mma8(D0[0][ni], afr[0], b00, b01);
            mma8(D0[1][ni], afr[1], b00, b01);
            uint32_t b10 = *(const uint32_t*)(bb + 9216 + tg * 4);
            uint32_t b11 = *(const uint32_t*)(bb + 9216 + 16 + tg * 4);
            mma8(D1[0][ni], afr[0], b10, b11);
            mma8(D1[1][ni], afr[1], b10, b11);
        }
    }
}

// ---------------- layer 1 kernel: K=896, NOUT=128, NT=2 in-CTA -------------
__global__ void __launch_bounds__(256, 3) gemm_spike_L1(
    const uint16_t* __restrict__ Min, const int8_t* __restrict__ Wq,
    const float* __restrict__ Sc, const float* __restrict__ bias,
    uint16_t* __restrict__ Mout)
{
    extern __shared__ __align__(16) char sm[];
    constexpr int OFF_A = 14336;          // masks 8*896*2 = 14336, then A 18432
    constexpr int OFF_B = OFF_A + 18432;  // 2 x 18432

    const uint32_t sbase = smem_u32(sm);
    const int tid = threadIdx.x;
    const int lane = tid & 31, wid = tid >> 5;
    const int wm2 = wid >> 1, wn = wid & 1;
    const int g = lane >> 2, tg = lane & 3;
    const int b0 = blockIdx.x * 8;

    {   // stage masks permuted: (m0,m2) | (m1,m3) per u64
        const uint4* msrc = (const uint4*)(Min + (size_t)b0 * KP1);
        uint4* mdst = (uint4*)sm;
        for (int u = tid; u < 896; u += 256) {
            uint4 v = msrc[u];
            uint4 o;
            o.x = __byte_perm(v.x, v.y, 0x5410);
            o.y = __byte_perm(v.x, v.y, 0x7632);
            o.z = __byte_perm(v.z, v.w, 0x5410);
            o.w = __byte_perm(v.z, v.w, 0x7632);
            mdst[u] = o;
        }
    }
    __syncthreads();

    for (int nt = 0; nt < 2; nt++) {
        const int n0 = nt * 64;
        int D0[2][4][4], D1[2][4][4];
#pragma unroll
        for (int mi = 0; mi < 2; mi++)
#pragma unroll
            for (int ni = 0; ni < 4; ni++)
#pragma unroll
                for (int r = 0; r < 4; r++) { D0[mi][ni][r] = 0; D1[mi][ni][r] = 0; }

        auto loadB = [&](int p, int buf) {
            for (int v = tid; v < 1024; v += 256) {
                int l = v >> 9, rem = v & 511, r = rem >> 3, c8 = rem & 7;
                const int8_t* src = Wq + ((size_t)l * 128 + n0 + r) * KP1 + p * 128 + c8 * 16;
                cpa16(sbase + OFF_B + buf * 18432 + l * 9216 + r * 144 + c8 * 16, src, 16u);
            }
            asm volatile("cp.async.commit_group;");
        };
        loadB(0, 0);

#pragma unroll 1
        for (int p = 0; p < 7; p++) {
            const int buf = p & 1;
            if (p < 6) loadB(p + 1, buf ^ 1);
            expand_perm(sm, sm + OFF_A, KP1 / 4, p, tid);
            if (p < 6) asm volatile("cp.async.wait_group 1;");
            else       asm volatile("cp.async.wait_group 0;");
            __syncthreads();
            mma_panel(sm + OFF_A, sm + OFF_B + buf * 18432, wm2, wn, g, tg, D0, D1);
            __syncthreads();
        }

        // combine (E-trick) -> scan buffer (pitch 68), overlays A+B region
        float* cs = (float*)(sm + OFF_A);
#pragma unroll
        for (int mi = 0; mi < 2; mi++)
#pragma unroll
            for (int ni = 0; ni < 4; ni++)
#pragma unroll
                for (int r = 0; r < 4; r++) {
                    int row = wm2 * 32 + mi * 16 + g + (r >> 1) * 8;
                    int col = wn * 32 + ni * 8 + tg * 2 + (r & 1);
                    float sc = __ldg(Sc + n0 + col) * (1.0f / 254.0f);
                    int E = D0[mi][ni][r] * 254 + D1[mi][ni][r];
                    cs[row * 68 + col] = sc * (float)E;
                }
        __syncthreads();

#pragma unroll
        for (int u = 0; u < 2; u++) {
            int pr = tid + 256 * u;
            int j = pr & 63, bl = pr >> 6;
            int jj = n0 + j;
            float bj = __ldg(bias + jj);
            const float* colp = cs + bl * 16 * 68 + j;
            float v = 0.0f;
            uint32_t msk = 0;
            bool flag = false;
#pragma unroll
            for (int t = 0; t < 16; t++) {
                v = (v + colp[t * 68]) + bj;
                flag |= (fabsf(v - 1.0f) < EPS);
                if (v >= 1.0f) { msk |= (1u << t); v -= 1.0f; }
            }
            int b = b0 + bl;
            Mout[(size_t)b * 128 + jj] = (uint16_t)msk;
            if (flag) {
                int s = atomicAdd(&g_cnt[0], 1);
                if (s < FCAP) g_flag[0][s] = ((uint32_t)b << 10) | (uint32_t)jj;
            }
        }
        __syncthreads();   // scan buffer reused by next tile's expansion
    }
}

// ---------------- K=128 layers: NT N-tiles looped in-CTA -------------------
template <int NT, int NOUT, bool IS_LAST, int LID>
__global__ void __launch_bounds__(256, 3) gemm_spike_K128(
    const uint16_t* __restrict__ Min, const int8_t* __restrict__ Wq,
    const float* __restrict__ Sc, const float* __restrict__ bias,
    uint16_t* __restrict__ Mout, float* __restrict__ Out)
{
    extern __shared__ __align__(16) char sm[];
    constexpr int OFF_A  = 2048;            // masks 8*128*2
    constexpr int OFF_B  = OFF_A + 18432;   // 2 x 18432
    constexpr int OFF_CS = OFF_B + 36864;   // 128 x 68 floats

    const uint32_t sbase = smem_u32(sm);
    const int tid = threadIdx.x;
    const int lane = tid & 31, wid = tid >> 5;
    const int wm2 = wid >> 1, wn = wid & 1;
    const int g = lane >> 2, tg = lane & 3;
    const int b0 = blockIdx.x * 8;

    {   // stage masks
        const uint4* msrc = (const uint4*)(Min + (size_t)b0 * 128);
        uint4* mdst = (uint4*)sm;
        for (int u = tid; u < 128; u += 256) mdst[u] = msrc[u];
    }

    auto loadB = [&](int nt, int buf) {
        const int n0 = nt * 64;
        for (int v = tid; v < 1024; v += 256) {
            int l = v >> 9, rem = v & 511, r = rem >> 3, c8 = rem & 7;
            int row = n0 + r;
            uint32_t ssz = (row < NOUT) ? 16u : 0u;
            int rc = row < NOUT ? row : 0;
            const int8_t* src = Wq + ((size_t)l * NOUT + rc) * 128 + c8 * 16;
            cpa16(sbase + OFF_B + buf * 18432 + l * 9216 + r * 144 + c8 * 16, src, ssz);
        }
        asm volatile("cp.async.commit_group;");
    };
    loadB(0, 0);
    __syncthreads();                        // masks visible
    expand_unperm((const uint16_t*)sm, sm + OFF_A, tid);  // A expanded ONCE
    __syncthreads();

#pragma unroll 1
    for (int nt = 0; nt < NT; nt++) {
        const int buf = nt & 1;
        const int n0 = nt * 64;
        if (nt + 1 < NT) loadB(nt + 1, buf ^ 1);
        if (nt + 1 < NT) asm volatile("cp.async.wait_group 1;");
        else             asm volatile("cp.async.wait_group 0;");
        __syncthreads();                    // B(nt) visible

        int D0[2][4][4], D1[2][4][4];
#pragma unroll
        for (int mi = 0; mi < 2; mi++)
#pragma unroll
            for (int ni = 0; ni < 4; ni++)
#pragma unroll
                for (int r = 0; r < 4; r++) { D0[mi][ni][r] = 0; D1[mi][ni][r] = 0; }

        mma_panel(sm + OFF_A, sm + OFF_B + buf * 18432, wm2, wn, g, tg, D0, D1);

        float* cs = (float*)(sm + OFF_CS);
#pragma unroll
        for (int mi = 0; mi < 2; mi++)
#pragma unroll
            for (int ni = 0; ni < 4; ni++)
#pragma unroll
                for (int r = 0; r < 4; r++) {
                    int row = wm2 * 32 + mi * 16 + g + (r >> 1) * 8;
                    int col = wn * 32 + ni * 8 + tg * 2 + (r & 1);
                    int jg = n0 + col;
                    float sc = __ldg(Sc + (jg < NOUT ? jg : 0)) * (1.0f / 254.0f);
                    int E = D0[mi][ni][r] * 254 + D1[mi][ni][r];
                    cs[row * 68 + col] = sc * (float)E;
                }
        __syncthreads();                    // cs complete

#pragma unroll
        for (int u = 0; u < 2; u++) {
            int pr = tid + 256 * u;
            int j = pr & 63, bl = pr >> 6;
            int jj = n0 + j;
            if (jj < NOUT) {
                float bj = __ldg(bias + jj);
                const float* colp = cs + bl * 16 * 68 + j;
                float v = 0.0f;
                uint32_t msk = 0;
                bool flag = false;
#pragma unroll
                for (int t = 0; t < 16; t++) {
                    v = (v + colp[t * 68]) + bj;
                    flag |= (fabsf(v - 1.0f) < EPS);
                    if (v >= 1.0f) { msk |= (1u << t); v -= 1.0f; }
                }
                int b = b0 + bl;
                if (IS_LAST)
                    Out[(size_t)b * NOUT + jj] = (float)__popc(msk) * 0.0625f;
                else
                    Mout[(size_t)b * NOUT + jj] = (uint16_t)msk;
                if (flag) {
                    int s = atomicAdd(&g_cnt[LID], 1);
                    if (s < FCAP) g_flag[LID][s] = ((uint32_t)b << 10) | (uint32_t)jj;
                }
            }
        }
        // next iteration's cs writes are separated by its post-wait barrier
    }
}

// ---------------- repair: t-parallel, warp = 2 flagged pairs ---------------
template <int KP, int K, int NOUT, bool IS_LAST, int LID>
__global__ void __launch_bounds__(256) repair_kernel(
    const uint16_t* __restrict__ Min, const float* __restrict__ W,
    const float* __restrict__ bias, uint16_t* __restrict__ Mout,
    float* __restrict__ Out)
{
    int n = g_cnt[LID];
    if (n > FCAP) n = FCAP;
    const int lane = threadIdx.x & 31;
    const int grp = lane >> 4, tl = lane & 15;
    const int wglob = (blockIdx.x * blockDim.x + threadIdx.x) >> 5;
    const int nwarps = (gridDim.x * blockDim.x) >> 5;

    for (int s0 = wglob * 2; s0 < n; s0 += nwarps * 2) {
        int s = s0 + grp;
        float acc = 0.0f;
        int b = 0, j = 0;
        bool active = (s < n);
        if (active) {
            uint32_t pk = g_flag[LID][s];
            b = (int)(pk >> 10); j = (int)(pk & 1023u);
            const uint16_t* mrow = Min + (size_t)b * KP;
            const float* wr = W + (size_t)j * K;
            const uint32_t bit = 1u << tl;
            for (int i = 0; i < K; i++) {
                unsigned m = mrow[i];
                if (m & bit) acc += wr[i];
            }
        }
        float bj = active ? bias[j] : 0.0f;
        float v = 0.0f;
        uint32_t msk = 0;
#pragma unroll
        for (int t = 0; t < TSTEPS; t++) {
            float a = __shfl_sync(0xFFFFFFFFu, acc, (lane & 16) + t);
            v = (v + a) + bj;
            if (v >= 1.0f) { msk |= (1u << t); v -= 1.0f; }
        }
        if (active && tl == 0) {
            if (IS_LAST)
                Out[(size_t)b * NOUT + j] = (float)__popc(msk) * 0.0625f;
            else
                Mout[(size_t)b * NOUT + j] = (uint16_t)msk;
        }
    }
}

// ---------------------------------------------------------------------------
extern "C" void kernel_launch(void* const* d_in, const int* in_sizes, int n_in,
                              void* d_out, int out_size)
{
    const float* features = (const float*)d_in[0];
    const float* W1 = (const float*)d_in[1];
    const float* b1 = (const float*)d_in[2];
    const float* W2 = (const float*)d_in[3];
    const float* b2 = (const float*)d_in[4];
    const float* W3 = (const float*)d_in[5];
    const float* b3 = (const float*)d_in[6];
    const float* W4 = (const float*)d_in[7];
    const float* b4 = (const float*)d_in[8];
    float* out = (float*)d_out;

    uint16_t *m0, *m1, *m2, *m3;
    int8_t *q1, *q2, *q3, *q4;
    float *s1, *s2, *s3, *s4;
    cudaGetSymbolAddress((void**)&m0, g_M0);
    cudaGetSymbolAddress((void**)&m1, g_M1);
    cudaGetSymbolAddress((void**)&m2, g_M2);
    cudaGetSymbolAddress((void**)&m3, g_M3);
    cudaGetSymbolAddress((void**)&q1, g_Q1);
    cudaGetSymbolAddress((void**)&q2, g_Q2);
    cudaGetSymbolAddress((void**)&q3, g_Q3);
    cudaGetSymbolAddress((void**)&q4, g_Q4);
    cudaGetSymbolAddress((void**)&s1, g_S1);
    cudaGetSymbolAddress((void**)&s2, g_S2);
    cudaGetSymbolAddress((void**)&s3, g_S3);
    cudaGetSymbolAddress((void**)&s4, g_S4);

    zero_cnt_kernel<<<1, 32>>>();
    enc_kernel<<<(BATCH * KP1 + 255) / 256, 256>>>(features);
    wsplit_all<<<1168, 32>>>(W1, W2, W3, W4);

    constexpr int SM_L1 = 14336 + 18432 + 2 * 18432;                    // 69632
    constexpr int SM_K  = 2048 + 18432 + 2 * 18432 + 128 * 68 * 4;      // 92160

    cudaFuncSetAttribute(gemm_spike_L1,
                         cudaFuncAttributeMaxDynamicSharedMemorySize, SM_L1);
    cudaFuncSetAttribute(gemm_spike_K128<2, 128, false, 1>,
                         cudaFuncAttributeMaxDynamicSharedMemorySize, SM_K);
    cudaFuncSetAttribute(gemm_spike_K128<2, 128, false, 2>,
                         cudaFuncAttributeMaxDynamicSharedMemorySize, SM_K);
    cudaFuncSetAttribute(gemm_spike_K128<13, 784, true, 3>,
                         cudaFuncAttributeMaxDynamicSharedMemorySize, SM_K);

    gemm_spike_L1<<<BATCH / 8, 256, SM_L1>>>(m0, q1, s1, b1, m1);
    repair_kernel<KP1, 784, 128, false, 0><<<296, 256>>>(m0, W1, b1, m1, nullptr);

    gemm_spike_K128<2, 128, false, 1><<<BATCH / 8, 256, SM_K>>>(m1, q2, s2, b2, m2, nullptr);
    repair_kernel<128, 128, 128, false, 1><<<296, 256>>>(m1, W2, b2, m2, nullptr);

    gemm_spike_K128<2, 128, false, 2><<<BATCH / 8, 256, SM_K>>>(m2, q3, s3, b3, m3, nullptr);
    repair_kernel<128, 128, 128, false, 2><<<296, 256>>>(m2, W3, b3, m3, nullptr);

    gemm_spike_K128<13, 784, true, 3><<<BATCH / 8, 256, SM_K>>>(m3, q4, s4, b4, nullptr, out);
    repair_kernel<128, 128, 784, true, 3><<<296, 256>>>(m3, W4, b4, nullptr, out);
}